// round 13
// baseline (speedup 1.0000x reference)
#include <cuda_runtime.h>
#include <cfloat>

#define TOT 8192
#define BN 16
#define C 64
#define K 20
#define CN 512
#define NW (BN*CN)
#define STEPS 8
#define NBLK 1024
#define BN_EPS 1e-5f
#define WSTR 400   // smem floats per walker: 22 cols x stride 17 = 374, pad->400

// ---- device scratch (static; no allocations) ----
__device__ float  g_xT[(size_t)BN*TOT*C];        // x transposed (b,node,ch) 32MB
__device__ float2 g_ssq[(size_t)BN*TOT];         // per-node (dot(x,w_lo), |x|^2)
__device__ float  g_curves[(size_t)STEPS*NW*C];  // [step][w][ch] 16MB
__device__ float  g_S[2][BN*2*CN];               // double-buffered softmax exchange
__device__ unsigned g_bar;                       // grid barrier counter

__device__ __forceinline__ float dot4(const float4& a, const float4& b) {
    return a.x*b.x + a.y*b.y + a.z*b.z + a.w*b.w;
}

// ---------------- fused prep: transpose + per-node (s, |x|^2) (validated) ----
__global__ __launch_bounds__(256)
void prep_kernel(const float* __restrict__ x, const float* __restrict__ agent_w) {
    __shared__ float tile[64][33];
    int b = blockIdx.y;
    int node0 = blockIdx.x * 32;
    int t = threadIdx.x;
    int ty = t >> 3;
    int tx = t & 7;

    const float* xb = x + (size_t)b * C * TOT;
    float4 v0 = __ldg((const float4*)(xb + (size_t)ty * TOT + node0) + tx);
    float4 v1 = __ldg((const float4*)(xb + (size_t)(ty + 32) * TOT + node0) + tx);
    tile[ty][tx*4+0] = v0.x; tile[ty][tx*4+1] = v0.y;
    tile[ty][tx*4+2] = v0.z; tile[ty][tx*4+3] = v0.w;
    tile[ty+32][tx*4+0] = v1.x; tile[ty+32][tx*4+1] = v1.y;
    tile[ty+32][tx*4+2] = v1.z; tile[ty+32][tx*4+3] = v1.w;
    __syncthreads();

    int node = t >> 3;
    int j = t & 7;
    float4 a = make_float4(tile[4*j+0][node], tile[4*j+1][node],
                           tile[4*j+2][node], tile[4*j+3][node]);
    float4 c = make_float4(tile[32+4*j+0][node], tile[32+4*j+1][node],
                           tile[32+4*j+2][node], tile[32+4*j+3][node]);
    float4* dst = (float4*)(g_xT + ((size_t)b * TOT + node0 + node) * C);
    dst[j] = a; dst[8 + j] = c;

    const float4* wv = (const float4*)agent_w;
    float4 wA = __ldg(&wv[j]), wB = __ldg(&wv[8 + j]);
    float s = dot4(a, wA) + dot4(c, wB);
    float q = dot4(a, a) + dot4(c, c);
    #pragma unroll
    for (int off = 1; off <= 4; off <<= 1) {
        s += __shfl_xor_sync(0xffffffffu, s, off);
        q += __shfl_xor_sync(0xffffffffu, q, off);
    }
    if (j == 0) g_ssq[(size_t)b * TOT + node0 + node] = make_float2(s, q);
}

// ---------------- persistent walk: all 8 steps; 16 lanes/walker, 8 walkers/block ----
// smem cols (stride 17): phase A: cvp k->col k (0..19), cvcf->20, cf2->21;
//                        phase B: cfp k->col k.
__global__ __launch_bounds__(128, 7)
void walk_persistent(
    const int* __restrict__ adj, const int* __restrict__ cur0,
    const float* __restrict__ agent_w,
    const float* __restrict__ agent_gamma, const float* __restrict__ agent_beta,
    const float* __restrict__ agent_mean,  const float* __restrict__ agent_var,
    const float* __restrict__ mom_w,
    const float* __restrict__ mom_gamma, const float* __restrict__ mom_beta,
    const float* __restrict__ mom_mean,  const float* __restrict__ mom_var)
{
    __shared__ float sm[8 * WSTR];
    int sub = threadIdx.x & 15;
    int wi  = threadIdx.x >> 4;
    int w = blockIdx.x * 8 + wi;
    int b = w >> 9;
    int n = w & 511;
    int smb = wi * WSTR;

    const float4* wv = (const float4*)agent_w;
    float4 wh = __ldg(&wv[16 + sub]);              // agent_w[64:128]

    float inv_a  = __ldg(agent_gamma) / sqrtf(__ldg(agent_var) + BN_EPS);
    float mean_a = __ldg(agent_mean);
    float beta_a = __ldg(agent_beta);

    const float* xTb = g_xT + (size_t)b * TOT * C;
    const float2* ssqb = g_ssq + (size_t)b * TOT;

    int cidx = __ldg(&cur0[w]);
    float4 cf4 = make_float4(0.f,0.f,0.f,0.f);
    float4 pf4 = cf4;

    for (int step = 0; step < STEPS; step++) {
        float4 cv4;
        float tpp, n1 = 0.f;

        if (step == 0) {
            pf4 = __ldg(&((const float4*)(xTb + (size_t)cidx * C))[sub]);
            tpp = dot4(pf4, wh);
            #pragma unroll
            for (int off = 1; off <= 8; off <<= 1)
                tpp += __shfl_xor_sync(0xffffffffu, tpp, off);
            cv4 = make_float4(0.f,0.f,0.f,0.f);
        } else {
            float2 aa = __ldcg(((const float2*)g_S[(step - 1) & 1]) + b * 512 + n);
            float a0 = aa.x, a1 = aa.y;
            pf4.x = cf4.x*a0 + pf4.x*a1;  pf4.y = cf4.y*a0 + pf4.y*a1;
            pf4.z = cf4.z*a0 + pf4.z*a1;  pf4.w = cf4.w*a0 + pf4.w*a1;
            cv4.x = cf4.x - pf4.x; cv4.y = cf4.y - pf4.y;
            cv4.z = cf4.z - pf4.z; cv4.w = cf4.w - pf4.w;

            float tppp = dot4(pf4, wh);
            float n1pp = dot4(cv4, cv4);
            #pragma unroll
            for (int off = 1; off <= 8; off <<= 1) {
                tppp += __shfl_xor_sync(0xffffffffu, tppp, off);
                n1pp += __shfl_xor_sync(0xffffffffu, n1pp, off);
            }
            tpp = tppp; n1 = sqrtf(n1pp);
        }

        const int* adjp = adj + ((size_t)b * TOT + cidx) * K;
        const int4* adj4 = (const int4*)adjp;

        // ---- lane-owned ssq loads (coalesced adj reads; hoisted) ----
        int oa0 = __ldg(&adjp[sub]);
        int oa1 = (sub < 4) ? __ldg(&adjp[16 + sub]) : oa0;
        float2 q0 = __ldg(&ssqb[oa0]);
        float2 q1 = __ldg(&ssqb[oa1]);

        float best; int ksel;

        if (step == 0) {
            best = (q0.x + tpp - mean_a) * inv_a + beta_a;  ksel = sub;
            if (sub < 4) {
                float l1 = (q1.x + tpp - mean_a) * inv_a + beta_a;
                if (l1 > best) { best = l1; ksel = 16 + sub; }
            }
        } else {
            // ---- gather 20 rows (256B coalesced each, full MLP) ----
            float cfp[K];
            #pragma unroll
            for (int q = 0; q < 5; q++) {
                int4 t4 = __ldg(&adj4[q]);
                float4 p0 = __ldg(&((const float4*)(xTb + (size_t)t4.x * C))[sub]);
                float4 p1 = __ldg(&((const float4*)(xTb + (size_t)t4.y * C))[sub]);
                float4 p2 = __ldg(&((const float4*)(xTb + (size_t)t4.z * C))[sub]);
                float4 p3 = __ldg(&((const float4*)(xTb + (size_t)t4.w * C))[sub]);
                sm[smb + 17*(4*q+0) + sub] = dot4(cv4, p0);
                sm[smb + 17*(4*q+1) + sub] = dot4(cv4, p1);
                sm[smb + 17*(4*q+2) + sub] = dot4(cv4, p2);
                sm[smb + 17*(4*q+3) + sub] = dot4(cv4, p3);
                cfp[4*q+0] = dot4(cf4, p0);
                cfp[4*q+1] = dot4(cf4, p1);
                cfp[4*q+2] = dot4(cf4, p2);
                cfp[4*q+3] = dot4(cf4, p3);
            }
            // cvcf / cf2 through SAME tree (=> cc exactly 0 on self-neighbors)
            sm[smb + 17*20 + sub] = dot4(cv4, cf4);
            sm[smb + 17*21 + sub] = dot4(cf4, cf4);
            __syncwarp();

            // ---- phase A: 16-way serial column sums (fixed order) for cv side ----
            int cS1 = (sub < 6) ? (16 + sub) : sub;
            float S0 = 0.f, S1 = 0.f;
            #pragma unroll
            for (int i = 0; i < 16; i++) {
                S0 += sm[smb + 17*sub + i];
                S1 += sm[smb + 17*cS1 + i];
            }
            float cvcf = __shfl_sync(0xffffffffu, S1, 4, 16);  // lane 4 owns col 20
            float cf2  = __shfl_sync(0xffffffffu, S1, 5, 16);  // lane 5 owns col 21
            __syncwarp();   // phase A reads complete before overwrite

            // ---- phase B: store cfp partials (constant cols), reduce ----
            #pragma unroll
            for (int k = 0; k < K; k++) sm[smb + 17*k + sub] = cfp[k];
            __syncwarp();
            int cT1 = (sub < 4) ? (16 + sub) : sub;
            float T0 = 0.f, T1 = 0.f;
            #pragma unroll
            for (int i = 0; i < 16; i++) {
                T0 += sm[smb + 17*sub + i];
                T1 += sm[smb + 17*cT1 + i];
            }

            // ---- lane-distributed epilogue (1-2 candidates per lane) ----
            {
                float lg = (q0.x + tpp - mean_a) * inv_a + beta_a;
                float cc = S0 - cvcf;
                float nn = q0.y - 2.f * T0 + cf2;
                float cosv = cc / fmaxf(n1 * sqrtf(nn), 1e-8f);
                lg *= fminf(fmaxf(1.f + cosv, 0.f), 1.f);
                best = lg; ksel = sub;
            }
            if (sub < 4) {
                float lg = (q1.x + tpp - mean_a) * inv_a + beta_a;
                float cc = S1 - cvcf;
                float nn = q1.y - 2.f * T1 + cf2;
                float cosv = cc / fmaxf(n1 * sqrtf(nn), 1e-8f);
                lg *= fminf(fmaxf(1.f + cosv, 0.f), 1.f);
                if (lg > best) { best = lg; ksel = 16 + sub; }
            }
        }

        // ---- argmax combine over 16 lanes (ties -> smallest k = first max) ----
        #pragma unroll
        for (int off = 1; off <= 8; off <<= 1) {
            float ob = __shfl_xor_sync(0xffffffffu, best, off);
            int   ok = __shfl_xor_sync(0xffffffffu, ksel, off);
            if (ob > best || (ob == best && ok < ksel)) { best = ob; ksel = ok; }
        }

        int nidx = __ldg(&adjp[ksel]);
        cf4 = __ldg(&((const float4*)(xTb + (size_t)nidx * C))[sub]);
        cidx = nidx;

        // ---- coalesced curve store (state stays in registers) ----
        ((float4*)(g_curves + ((size_t)step * NW + w) * C))[sub] = cf4;

        if (step < STEPS - 1) {
            const float4* mv = (const float4*)mom_w;   // 2 rows x 32 float4
            float l0 = dot4(cf4, __ldg(&mv[sub]))      + dot4(pf4, __ldg(&mv[16 + sub]));
            float l1 = dot4(cf4, __ldg(&mv[32 + sub])) + dot4(pf4, __ldg(&mv[48 + sub]));
            #pragma unroll
            for (int off = 1; off <= 8; off <<= 1) {
                l0 += __shfl_xor_sync(0xffffffffu, l0, off);
                l1 += __shfl_xor_sync(0xffffffffu, l1, off);
            }
            if (sub == 0) {
                float inv0 = __ldg(&mom_gamma[0]) / sqrtf(__ldg(&mom_var[0]) + BN_EPS);
                float inv1 = __ldg(&mom_gamma[1]) / sqrtf(__ldg(&mom_var[1]) + BN_EPS);
                float m0 = (l0 - __ldg(&mom_mean[0])) * inv0 + __ldg(&mom_beta[0]);
                float m1 = (l1 - __ldg(&mom_mean[1])) * inv1 + __ldg(&mom_beta[1]);
                float mx = fmaxf(m0, m1);
                float e0 = expf(m0 - mx), e1 = expf(m1 - mx);
                float s = e0 + e1;
                g_S[step & 1][b * 1024 + n]       = e0 / s;
                g_S[step & 1][b * 1024 + 512 + n] = e1 / s;
            }
            // ---- grid barrier (1024 blocks resident: 7/SM x 148 = 1036 slots) ----
            __threadfence();
            __syncthreads();
            if (threadIdx.x == 0) {
                atomicAdd(&g_bar, 1u);
                unsigned target = (unsigned)(step + 1) * NBLK;
                while (*((volatile unsigned*)&g_bar) < target) { }
            }
            __syncthreads();
        }
    }
}

// ---------------- reorder: g_curves[step][w][ch] -> out[b][ch][n][step] ----------------
__global__ __launch_bounds__(256)
void reorder_kernel(float* __restrict__ out) {
    __shared__ float tile[16][8 * C + 1];
    int b = blockIdx.x >> 5;
    int n0 = (blockIdx.x & 31) * 16;
    int t = threadIdx.x;

    #pragma unroll
    for (int step = 0; step < STEPS; step++) {
        #pragma unroll
        for (int i4 = 0; i4 < 4; i4++) {
            int i = i4 * 4 + (t >> 6);
            int ch = t & 63;
            int w = b * CN + n0 + i;
            tile[i][step * 64 + ch] =
                g_curves[((size_t)step * NW + w) * C + ch];
        }
    }
    __syncthreads();

    int i = t & 15, ch0 = t >> 4;
    #pragma unroll
    for (int cc = 0; cc < 4; cc++) {
        int ch = ch0 + cc * 16;
        float v[8];
        #pragma unroll
        for (int s = 0; s < STEPS; s++) v[s] = tile[i][s * 64 + ch];
        float4* dst = (float4*)(out +
            ((((size_t)b * C + ch) * CN) + n0 + i) * STEPS);
        dst[0] = make_float4(v[0], v[1], v[2], v[3]);
        dst[1] = make_float4(v[4], v[5], v[6], v[7]);
    }
}

extern "C" void kernel_launch(void* const* d_in, const int* in_sizes, int n_in,
                              void* d_out, int out_size) {
    const float* x          = (const float*)d_in[1];
    const int*   adj        = (const int*)  d_in[2];
    const int*   cur        = (const int*)  d_in[3];
    const float* agent_w    = (const float*)d_in[4];
    const float* agent_gamma= (const float*)d_in[5];
    const float* agent_beta = (const float*)d_in[6];
    const float* agent_mean = (const float*)d_in[7];
    const float* agent_var  = (const float*)d_in[8];
    const float* mom_w      = (const float*)d_in[9];
    const float* mom_gamma  = (const float*)d_in[10];
    const float* mom_beta   = (const float*)d_in[11];
    const float* mom_mean   = (const float*)d_in[12];
    const float* mom_var    = (const float*)d_in[13];
    float* out = (float*)d_out;

    // reset grid-barrier counter (memset node is graph-capturable)
    void* bar_addr = nullptr;
    cudaGetSymbolAddress(&bar_addr, g_bar);
    cudaMemsetAsync(bar_addr, 0, sizeof(unsigned));

    dim3 pg(TOT / 32, BN);
    prep_kernel<<<pg, 256>>>(x, agent_w);

    walk_persistent<<<NBLK, 128>>>(adj, cur, agent_w, agent_gamma, agent_beta,
        agent_mean, agent_var, mom_w, mom_gamma, mom_beta, mom_mean, mom_var);

    reorder_kernel<<<BN * (CN / 16), 256>>>(out);
}

// round 15
// speedup vs baseline: 1.0561x; 1.0561x over previous
#include <cuda_runtime.h>
#include <cfloat>

#define TOT 8192
#define BN 16
#define C 64
#define K 20
#define CN 512
#define NW (BN*CN)
#define STEPS 8
#define BN_EPS 1e-5f
#define WSTR 416   // smem floats per walker: 22 cols x stride 17 = 374, pad->416

// ---- device scratch (static; no allocations) ----
__device__ float  g_xT[(size_t)BN*TOT*C];        // x transposed (b,node,ch) 32MB
__device__ float2 g_ssq[(size_t)BN*TOT];         // per-node (dot(x,w_lo), |x|^2)
__device__ float  g_curves[(size_t)STEPS*NW*C];  // [step][w][ch] 16MB
__device__ float  g_curf[(size_t)NW*C];
__device__ float  g_pref[(size_t)NW*C];
__device__ int    g_curidx[NW];
__device__ float  g_S[BN*2*CN];                  // softmax exchange

__device__ __forceinline__ float dot4(const float4& a, const float4& b) {
    return a.x*b.x + a.y*b.y + a.z*b.z + a.w*b.w;
}

// ---------------- fused prep: transpose + per-node (s, |x|^2) (validated) ----
__global__ __launch_bounds__(256)
void prep_kernel(const float* __restrict__ x, const float* __restrict__ agent_w) {
    __shared__ float tile[64][33];
    int b = blockIdx.y;
    int node0 = blockIdx.x * 32;
    int t = threadIdx.x;
    int ty = t >> 3;
    int tx = t & 7;

    const float* xb = x + (size_t)b * C * TOT;
    float4 v0 = __ldg((const float4*)(xb + (size_t)ty * TOT + node0) + tx);
    float4 v1 = __ldg((const float4*)(xb + (size_t)(ty + 32) * TOT + node0) + tx);
    tile[ty][tx*4+0] = v0.x; tile[ty][tx*4+1] = v0.y;
    tile[ty][tx*4+2] = v0.z; tile[ty][tx*4+3] = v0.w;
    tile[ty+32][tx*4+0] = v1.x; tile[ty+32][tx*4+1] = v1.y;
    tile[ty+32][tx*4+2] = v1.z; tile[ty+32][tx*4+3] = v1.w;
    __syncthreads();

    int node = t >> 3;
    int j = t & 7;
    float4 a = make_float4(tile[4*j+0][node], tile[4*j+1][node],
                           tile[4*j+2][node], tile[4*j+3][node]);
    float4 c = make_float4(tile[32+4*j+0][node], tile[32+4*j+1][node],
                           tile[32+4*j+2][node], tile[32+4*j+3][node]);
    float4* dst = (float4*)(g_xT + ((size_t)b * TOT + node0 + node) * C);
    dst[j] = a; dst[8 + j] = c;

    const float4* wv = (const float4*)agent_w;
    float4 wA = __ldg(&wv[j]), wB = __ldg(&wv[8 + j]);
    float s = dot4(a, wA) + dot4(c, wB);
    float q = dot4(a, a) + dot4(c, c);
    #pragma unroll
    for (int off = 1; off <= 4; off <<= 1) {
        s += __shfl_xor_sync(0xffffffffu, s, off);
        q += __shfl_xor_sync(0xffffffffu, q, off);
    }
    if (j == 0) g_ssq[(size_t)b * TOT + node0 + node] = make_float2(s, q);
}

// ---------------- one walk step; warp = walker (32 lanes), 4 walkers/block ----
// lane = (half, sub): half = lane>>4 owns neighbors [10*half,10*half+10),
// sub = lane&15 owns channels [4*sub..4*sub+3].
// smem cols (stride 17): phase A: cvp k->col k (0..19), cvcf->20, cf2->21;
//                        phase B: cfp k->col k.
// tpp / n1 via 16-lane butterfly (bitwise-identical to R12's tree).
template<bool FIRST>
__global__ __launch_bounds__(128)
void walk_step_kernel(
    const int* __restrict__ adj, const int* __restrict__ cur0,
    const float* __restrict__ agent_w,
    const float* __restrict__ agent_gamma, const float* __restrict__ agent_beta,
    const float* __restrict__ agent_mean,  const float* __restrict__ agent_var,
    const float* __restrict__ mom_w,
    const float* __restrict__ mom_gamma, const float* __restrict__ mom_beta,
    const float* __restrict__ mom_mean,  const float* __restrict__ mom_var,
    int step)
{
    __shared__ float sm[4 * WSTR];
    int lane = threadIdx.x & 31;
    int sub  = lane & 15;
    int half = lane >> 4;
    int wi   = threadIdx.x >> 5;
    int w = blockIdx.x * 4 + wi;
    int b = w >> 9;
    int n = w & 511;
    int smb = wi * WSTR;

    const float4* wv = (const float4*)agent_w;
    float4 wh = __ldg(&wv[16 + sub]);              // agent_w[64:128]

    float inv_a  = __ldg(agent_gamma) / sqrtf(__ldg(agent_var) + BN_EPS);
    float mean_a = __ldg(agent_mean);
    float beta_a = __ldg(agent_beta);

    const float* xTb = g_xT + (size_t)b * TOT * C;
    const float2* ssqb = g_ssq + (size_t)b * TOT;

    float4 cf4, pf4, cv4;
    int cidx;
    float tpp, n1 = 0.f;

    if (FIRST) {
        cidx = __ldg(&cur0[w]);
        pf4 = __ldg(&((const float4*)(xTb + (size_t)cidx * C))[sub]);
        tpp = dot4(pf4, wh);
        #pragma unroll
        for (int off = 1; off <= 8; off <<= 1)
            tpp += __shfl_xor_sync(0xffffffffu, tpp, off);
        cf4 = make_float4(0.f,0.f,0.f,0.f); cv4 = cf4;
    } else {
        cidx = g_curidx[w];
        cf4 = ((const float4*)(g_curf + (size_t)w * C))[sub];
        pf4 = ((const float4*)(g_pref + (size_t)w * C))[sub];
        float2 aa = ((const float2*)g_S)[b * 512 + n];   // entries 2n, 2n+1
        float a0 = aa.x, a1 = aa.y;
        pf4.x = cf4.x*a0 + pf4.x*a1;  pf4.y = cf4.y*a0 + pf4.y*a1;
        pf4.z = cf4.z*a0 + pf4.z*a1;  pf4.w = cf4.w*a0 + pf4.w*a1;
        cv4.x = cf4.x - pf4.x; cv4.y = cf4.y - pf4.y;
        cv4.z = cf4.z - pf4.z; cv4.w = cf4.w - pf4.w;

        // R12-bitwise butterfly trees for tpp / n1 (identical in both halves)
        float tppp = dot4(pf4, wh);
        float n1pp = dot4(cv4, cv4);
        #pragma unroll
        for (int off = 1; off <= 8; off <<= 1) {
            tppp += __shfl_xor_sync(0xffffffffu, tppp, off);
            n1pp += __shfl_xor_sync(0xffffffffu, n1pp, off);
        }
        tpp = tppp; n1 = sqrtf(n1pp);
    }

    const int* adjp = adj + ((size_t)b * TOT + cidx) * K;

    // ---- lane-owned candidate: lane k<20 owns neighbor k ----
    int myk = (lane < K) ? lane : 0;
    int oa = __ldg(&adjp[myk]);
    float2 q = __ldg(&ssqb[oa]);

    float best = -FLT_MAX; int ksel = 0x7fffffff;

    if (FIRST) {
        if (lane < K) {
            best = (q.x + tpp - mean_a) * inv_a + beta_a;
            ksel = lane;
        }
    } else {
        // ---- gathers: half h covers neighbors 10h..10h+9 (256B rows, full MLP) ----
        float cfp[10];
        #pragma unroll
        for (int j = 0; j < 10; j++) {
            int kk = 10 * half + j;
            int idx = __ldg(&adjp[kk]);
            float4 p = __ldg(&((const float4*)(xTb + (size_t)idx * C))[sub]);
            sm[smb + 17*kk + sub] = dot4(cv4, p);
            cfp[j] = dot4(cf4, p);
        }
        // cvcf / cf2 partials (half 0 writes; same dot tree as cvp partials)
        if (half == 0) {
            sm[smb + 17*20 + sub] = dot4(cv4, cf4);   // cvcf
            sm[smb + 17*21 + sub] = dot4(cf4, cf4);   // cf2
        }
        __syncwarp();

        // ---- phase A: lane k sums col k (k<22), fixed order i=0..15 ----
        float SA = 0.f;
        if (lane < 22) {
            #pragma unroll
            for (int i = 0; i < 16; i++) SA += sm[smb + 17*lane + i];
        }
        float cvcf = __shfl_sync(0xffffffffu, SA, 20);
        float cf2  = __shfl_sync(0xffffffffu, SA, 21);
        __syncwarp();   // phase A reads complete before overwrite

        // ---- phase B: store cfp partials, lane k sums col k (k<20) ----
        #pragma unroll
        for (int j = 0; j < 10; j++)
            sm[smb + 17*(10*half + j) + sub] = cfp[j];
        __syncwarp();
        float SB = 0.f;
        if (lane < K) {
            #pragma unroll
            for (int i = 0; i < 16; i++) SB += sm[smb + 17*lane + i];
        }

        // ---- one candidate per lane (formula text identical to R12) ----
        if (lane < K) {
            float lg = (q.x + tpp - mean_a) * inv_a + beta_a;
            float cc = SA - cvcf;
            float nn = q.y - 2.f * SB + cf2;
            float cosv = cc / fmaxf(n1 * sqrtf(nn), 1e-8f);
            lg *= fminf(fmaxf(1.f + cosv, 0.f), 1.f);
            best = lg; ksel = lane;
        }
    }

    // ---- argmax over 32 lanes (ties -> smallest k = first max) ----
    #pragma unroll
    for (int off = 1; off <= 16; off <<= 1) {
        float ob = __shfl_xor_sync(0xffffffffu, best, off);
        int   ok = __shfl_xor_sync(0xffffffffu, ksel, off);
        if (ob > best || (ob == best && ok < ksel)) { best = ob; ksel = ok; }
    }

    int nidx = __ldg(&adjp[ksel]);
    cf4 = __ldg(&((const float4*)(xTb + (size_t)nidx * C))[sub]);

    // ---- coalesced curve store + persist state (half 0 writes) ----
    if (half == 0) {
        ((float4*)(g_curves + ((size_t)step * NW + w) * C))[sub] = cf4;
        ((float4*)(g_curf + (size_t)w * C))[sub] = cf4;
        ((float4*)(g_pref + (size_t)w * C))[sub] = pf4;
    }
    if (lane == 0) g_curidx[w] = nidx;

    if (step < STEPS - 1) {
        const float4* mv = (const float4*)mom_w;   // 2 rows x 32 float4
        float l0 = dot4(cf4, __ldg(&mv[sub]))      + dot4(pf4, __ldg(&mv[16 + sub]));
        float l1 = dot4(cf4, __ldg(&mv[32 + sub])) + dot4(pf4, __ldg(&mv[48 + sub]));
        #pragma unroll
        for (int off = 1; off <= 8; off <<= 1) {
            l0 += __shfl_xor_sync(0xffffffffu, l0, off);
            l1 += __shfl_xor_sync(0xffffffffu, l1, off);
        }
        if (lane == 0) {
            float inv0 = __ldg(&mom_gamma[0]) / sqrtf(__ldg(&mom_var[0]) + BN_EPS);
            float inv1 = __ldg(&mom_gamma[1]) / sqrtf(__ldg(&mom_var[1]) + BN_EPS);
            float m0 = (l0 - __ldg(&mom_mean[0])) * inv0 + __ldg(&mom_beta[0]);
            float m1 = (l1 - __ldg(&mom_mean[1])) * inv1 + __ldg(&mom_beta[1]);
            float mx = fmaxf(m0, m1);
            float e0 = expf(m0 - mx), e1 = expf(m1 - mx);
            float s = e0 + e1;
            g_S[b * 1024 + n]       = e0 / s;
            g_S[b * 1024 + 512 + n] = e1 / s;
        }
    }
}

// ---------------- reorder: g_curves[step][w][ch] -> out[b][ch][n][step] ----------------
__global__ __launch_bounds__(256)
void reorder_kernel(float* __restrict__ out) {
    __shared__ float tile[16][8 * C + 1];
    int b = blockIdx.x >> 5;
    int n0 = (blockIdx.x & 31) * 16;
    int t = threadIdx.x;

    #pragma unroll
    for (int step = 0; step < STEPS; step++) {
        #pragma unroll
        for (int i4 = 0; i4 < 4; i4++) {
            int i = i4 * 4 + (t >> 6);
            int ch = t & 63;
            int w = b * CN + n0 + i;
            tile[i][step * 64 + ch] =
                g_curves[((size_t)step * NW + w) * C + ch];
        }
    }
    __syncthreads();

    int i = t & 15, ch0 = t >> 4;
    #pragma unroll
    for (int cc = 0; cc < 4; cc++) {
        int ch = ch0 + cc * 16;
        float v[8];
        #pragma unroll
        for (int s = 0; s < STEPS; s++) v[s] = tile[i][s * 64 + ch];
        float4* dst = (float4*)(out +
            ((((size_t)b * C + ch) * CN) + n0 + i) * STEPS);
        dst[0] = make_float4(v[0], v[1], v[2], v[3]);
        dst[1] = make_float4(v[4], v[5], v[6], v[7]);
    }
}

extern "C" void kernel_launch(void* const* d_in, const int* in_sizes, int n_in,
                              void* d_out, int out_size) {
    const float* x          = (const float*)d_in[1];
    const int*   adj        = (const int*)  d_in[2];
    const int*   cur        = (const int*)  d_in[3];
    const float* agent_w    = (const float*)d_in[4];
    const float* agent_gamma= (const float*)d_in[5];
    const float* agent_beta = (const float*)d_in[6];
    const float* agent_mean = (const float*)d_in[7];
    const float* agent_var  = (const float*)d_in[8];
    const float* mom_w      = (const float*)d_in[9];
    const float* mom_gamma  = (const float*)d_in[10];
    const float* mom_beta   = (const float*)d_in[11];
    const float* mom_mean   = (const float*)d_in[12];
    const float* mom_var    = (const float*)d_in[13];
    float* out = (float*)d_out;

    dim3 pg(TOT / 32, BN);
    prep_kernel<<<pg, 256>>>(x, agent_w);

    int blocks = NW / 4;   // 2048 blocks of 128 threads (warp = walker)
    walk_step_kernel<true><<<blocks, 128>>>(adj, cur, agent_w, agent_gamma,
        agent_beta, agent_mean, agent_var, mom_w, mom_gamma, mom_beta,
        mom_mean, mom_var, 0);
    for (int s = 1; s < STEPS; s++) {
        walk_step_kernel<false><<<blocks, 128>>>(adj, cur, agent_w, agent_gamma,
            agent_beta, agent_mean, agent_var, mom_w, mom_gamma, mom_beta,
            mom_mean, mom_var, s);
    }
    reorder_kernel<<<BN * (CN / 16), 256>>>(out);
}

// round 16
// speedup vs baseline: 1.1706x; 1.1084x over previous
#include <cuda_runtime.h>
#include <cfloat>

#define TOT 8192
#define BN 16
#define C 64
#define K 20
#define CN 512
#define NW (BN*CN)
#define STEPS 8
#define BN_EPS 1e-5f
#define WSTR 400   // smem floats per walker: 22 cols x stride 17 = 374, pad->400

// ---- device scratch (static; no allocations) ----
__device__ float  g_xT[(size_t)BN*TOT*C];        // x transposed (b,node,ch) 32MB
__device__ float2 g_ssq[(size_t)BN*TOT];         // per-node (dot(x,w_lo), |x|^2)
__device__ float  g_curves[(size_t)STEPS*NW*C];  // [step][w][ch] 16MB
__device__ float  g_curf[(size_t)NW*C];
__device__ float  g_pref[(size_t)NW*C];
__device__ int    g_adjc[(size_t)NW*K];          // prefetched adj row of next node
__device__ float2 g_ssqc[(size_t)NW*K];          // prefetched ssq of those neighbors
__device__ float  g_S[BN*2*CN];                  // softmax exchange

__device__ __forceinline__ float dot4(const float4& a, const float4& b) {
    return a.x*b.x + a.y*b.y + a.z*b.z + a.w*b.w;
}

// ---------------- fused prep: transpose + per-node (s, |x|^2) (validated) ----
__global__ __launch_bounds__(256)
void prep_kernel(const float* __restrict__ x, const float* __restrict__ agent_w) {
    __shared__ float tile[64][33];
    int b = blockIdx.y;
    int node0 = blockIdx.x * 32;
    int t = threadIdx.x;
    int ty = t >> 3;
    int tx = t & 7;

    const float* xb = x + (size_t)b * C * TOT;
    float4 v0 = __ldg((const float4*)(xb + (size_t)ty * TOT + node0) + tx);
    float4 v1 = __ldg((const float4*)(xb + (size_t)(ty + 32) * TOT + node0) + tx);
    tile[ty][tx*4+0] = v0.x; tile[ty][tx*4+1] = v0.y;
    tile[ty][tx*4+2] = v0.z; tile[ty][tx*4+3] = v0.w;
    tile[ty+32][tx*4+0] = v1.x; tile[ty+32][tx*4+1] = v1.y;
    tile[ty+32][tx*4+2] = v1.z; tile[ty+32][tx*4+3] = v1.w;
    __syncthreads();

    int node = t >> 3;
    int j = t & 7;
    float4 a = make_float4(tile[4*j+0][node], tile[4*j+1][node],
                           tile[4*j+2][node], tile[4*j+3][node]);
    float4 c = make_float4(tile[32+4*j+0][node], tile[32+4*j+1][node],
                           tile[32+4*j+2][node], tile[32+4*j+3][node]);
    float4* dst = (float4*)(g_xT + ((size_t)b * TOT + node0 + node) * C);
    dst[j] = a; dst[8 + j] = c;

    const float4* wv = (const float4*)agent_w;
    float4 wA = __ldg(&wv[j]), wB = __ldg(&wv[8 + j]);
    float s = dot4(a, wA) + dot4(c, wB);
    float q = dot4(a, a) + dot4(c, c);
    #pragma unroll
    for (int off = 1; off <= 4; off <<= 1) {
        s += __shfl_xor_sync(0xffffffffu, s, off);
        q += __shfl_xor_sync(0xffffffffu, q, off);
    }
    if (j == 0) g_ssq[(size_t)b * TOT + node0 + node] = make_float2(s, q);
}

// ---------------- one walk step; 16 lanes/walker, 8 walkers/block (R12 body) ----
// lane sub (0..15) owns channels [4*sub..4*sub+3].
// smem cols (stride 17): phase A: cvp k->col k (0..19), cvcf->20, cf2->21;
//                        phase B: cfp k->col k.
// Cross-step prefetch: adj row + ssq of the selected node stored at tail,
// consumed at next step's head (values bitwise-identical to direct loads).
template<bool FIRST>
__global__ __launch_bounds__(128)
void walk_step_kernel(
    const int* __restrict__ adj, const int* __restrict__ cur0,
    const float* __restrict__ agent_w,
    const float* __restrict__ agent_gamma, const float* __restrict__ agent_beta,
    const float* __restrict__ agent_mean,  const float* __restrict__ agent_var,
    const float* __restrict__ mom_w,
    const float* __restrict__ mom_gamma, const float* __restrict__ mom_beta,
    const float* __restrict__ mom_mean,  const float* __restrict__ mom_var,
    int step)
{
    __shared__ float sm[8 * WSTR];
    int sub = threadIdx.x & 15;
    int wi  = threadIdx.x >> 4;
    int w = blockIdx.x * 8 + wi;
    int b = w >> 9;
    int n = w & 511;
    int smb = wi * WSTR;

    const float4* wv = (const float4*)agent_w;
    float4 wh = __ldg(&wv[16 + sub]);              // agent_w[64:128]

    float inv_a  = __ldg(agent_gamma) / sqrtf(__ldg(agent_var) + BN_EPS);
    float mean_a = __ldg(agent_mean);
    float beta_a = __ldg(agent_beta);

    const float* xTb = g_xT + (size_t)b * TOT * C;
    const float2* ssqb = g_ssq + (size_t)b * TOT;

    float4 cf4, pf4, cv4;
    float tpp, n1 = 0.f;

    // candidate sources (FIRST: direct; else: prefetched scratch)
    const int* adjc;
    int oa0;
    float2 q0, q1;

    if (FIRST) {
        int cidx = __ldg(&cur0[w]);
        pf4 = __ldg(&((const float4*)(xTb + (size_t)cidx * C))[sub]);
        tpp = dot4(pf4, wh);
        #pragma unroll
        for (int off = 1; off <= 8; off <<= 1)
            tpp += __shfl_xor_sync(0xffffffffu, tpp, off);
        cf4 = make_float4(0.f,0.f,0.f,0.f); cv4 = cf4;
        adjc = adj + ((size_t)b * TOT + cidx) * K;
        oa0 = __ldg(&adjc[sub]);
        int oa1 = (sub < 4) ? __ldg(&adjc[16 + sub]) : oa0;
        q0 = __ldg(&ssqb[oa0]);
        q1 = __ldg(&ssqb[oa1]);
    } else {
        adjc = g_adjc + (size_t)w * K;
        // prefetched head loads (no chained L2 round trips)
        oa0 = adjc[sub];
        q0 = g_ssqc[(size_t)w * K + sub];
        q1 = (sub < 4) ? g_ssqc[(size_t)w * K + 16 + sub] : q0;

        cf4 = ((const float4*)(g_curf + (size_t)w * C))[sub];
        pf4 = ((const float4*)(g_pref + (size_t)w * C))[sub];
        float2 aa = ((const float2*)g_S)[b * 512 + n];   // entries 2n, 2n+1
        float a0 = aa.x, a1 = aa.y;
        pf4.x = cf4.x*a0 + pf4.x*a1;  pf4.y = cf4.y*a0 + pf4.y*a1;
        pf4.z = cf4.z*a0 + pf4.z*a1;  pf4.w = cf4.w*a0 + pf4.w*a1;
        cv4.x = cf4.x - pf4.x; cv4.y = cf4.y - pf4.y;
        cv4.z = cf4.z - pf4.z; cv4.w = cf4.w - pf4.w;

        float tppp = dot4(pf4, wh);
        float n1pp = dot4(cv4, cv4);
        #pragma unroll
        for (int off = 1; off <= 8; off <<= 1) {
            tppp += __shfl_xor_sync(0xffffffffu, tppp, off);
            n1pp += __shfl_xor_sync(0xffffffffu, n1pp, off);
        }
        tpp = tppp; n1 = sqrtf(n1pp);
    }

    float best; int ksel;

    if (FIRST) {
        best = (q0.x + tpp - mean_a) * inv_a + beta_a;  ksel = sub;
        if (sub < 4) {
            float l1 = (q1.x + tpp - mean_a) * inv_a + beta_a;
            if (l1 > best) { best = l1; ksel = 16 + sub; }
        }
    } else {
        // ---- gather 20 rows (256B coalesced each, full MLP) ----
        const int4* adj4 = (const int4*)adjc;
        float cfp[K];
        #pragma unroll
        for (int q = 0; q < 5; q++) {
            int4 t4 = adj4[q];
            float4 p0 = __ldg(&((const float4*)(xTb + (size_t)t4.x * C))[sub]);
            float4 p1 = __ldg(&((const float4*)(xTb + (size_t)t4.y * C))[sub]);
            float4 p2 = __ldg(&((const float4*)(xTb + (size_t)t4.z * C))[sub]);
            float4 p3 = __ldg(&((const float4*)(xTb + (size_t)t4.w * C))[sub]);
            sm[smb + 17*(4*q+0) + sub] = dot4(cv4, p0);
            sm[smb + 17*(4*q+1) + sub] = dot4(cv4, p1);
            sm[smb + 17*(4*q+2) + sub] = dot4(cv4, p2);
            sm[smb + 17*(4*q+3) + sub] = dot4(cv4, p3);
            cfp[4*q+0] = dot4(cf4, p0);
            cfp[4*q+1] = dot4(cf4, p1);
            cfp[4*q+2] = dot4(cf4, p2);
            cfp[4*q+3] = dot4(cf4, p3);
        }
        // cvcf / cf2 through SAME tree (=> cc exactly 0 on self-neighbors)
        sm[smb + 17*20 + sub] = dot4(cv4, cf4);
        sm[smb + 17*21 + sub] = dot4(cf4, cf4);
        __syncwarp();

        // ---- phase A: 16-way serial column sums (fixed order) for cv side ----
        int cS1 = (sub < 6) ? (16 + sub) : sub;
        float S0 = 0.f, S1 = 0.f;
        #pragma unroll
        for (int i = 0; i < 16; i++) {
            S0 += sm[smb + 17*sub + i];
            S1 += sm[smb + 17*cS1 + i];
        }
        float cvcf = __shfl_sync(0xffffffffu, S1, 4, 16);  // lane 4 owns col 20
        float cf2  = __shfl_sync(0xffffffffu, S1, 5, 16);  // lane 5 owns col 21
        __syncwarp();   // phase A reads complete before overwrite

        // ---- phase B: store cfp partials (constant cols), reduce ----
        #pragma unroll
        for (int k = 0; k < K; k++) sm[smb + 17*k + sub] = cfp[k];
        __syncwarp();
        int cT1 = (sub < 4) ? (16 + sub) : sub;
        float T0 = 0.f, T1 = 0.f;
        #pragma unroll
        for (int i = 0; i < 16; i++) {
            T0 += sm[smb + 17*sub + i];
            T1 += sm[smb + 17*cT1 + i];
        }

        // ---- lane-distributed epilogue (1-2 candidates per lane) ----
        {
            float lg = (q0.x + tpp - mean_a) * inv_a + beta_a;
            float cc = S0 - cvcf;
            float nn = q0.y - 2.f * T0 + cf2;
            float cosv = cc / fmaxf(n1 * sqrtf(nn), 1e-8f);
            lg *= fminf(fmaxf(1.f + cosv, 0.f), 1.f);
            best = lg; ksel = sub;
        }
        if (sub < 4) {
            float lg = (q1.x + tpp - mean_a) * inv_a + beta_a;
            float cc = S1 - cvcf;
            float nn = q1.y - 2.f * T1 + cf2;
            float cosv = cc / fmaxf(n1 * sqrtf(nn), 1e-8f);
            lg *= fminf(fmaxf(1.f + cosv, 0.f), 1.f);
            if (lg > best) { best = lg; ksel = 16 + sub; }
        }
    }

    // ---- argmax combine over 16 lanes (ties -> smallest k = first max) ----
    #pragma unroll
    for (int off = 1; off <= 8; off <<= 1) {
        float ob = __shfl_xor_sync(0xffffffffu, best, off);
        int   ok = __shfl_xor_sync(0xffffffffu, ksel, off);
        if (ob > best || (ob == best && ok < ksel)) { best = ob; ksel = ok; }
    }

    int nidx = FIRST ? __ldg(&adjc[ksel]) : adjc[ksel];
    cf4 = __ldg(&((const float4*)(xTb + (size_t)nidx * C))[sub]);

    // ---- coalesced curve store + persist state (256B rows) ----
    ((float4*)(g_curves + ((size_t)step * NW + w) * C))[sub] = cf4;
    ((float4*)(g_curf + (size_t)w * C))[sub] = cf4;
    ((float4*)(g_pref + (size_t)w * C))[sub] = pf4;

    if (step < STEPS - 1) {
        // ---- prefetch next step's adjacency + ssq (off the next critical path) ----
        {
            const int* adjn = adj + ((size_t)b * TOT + nidx) * K;
            int pa0 = __ldg(&adjn[sub]);
            g_adjc[(size_t)w * K + sub] = pa0;
            g_ssqc[(size_t)w * K + sub] = __ldg(&ssqb[pa0]);
            if (sub < 4) {
                int pa1 = __ldg(&adjn[16 + sub]);
                g_adjc[(size_t)w * K + 16 + sub] = pa1;
                g_ssqc[(size_t)w * K + 16 + sub] = __ldg(&ssqb[pa1]);
            }
        }

        const float4* mv = (const float4*)mom_w;   // 2 rows x 32 float4
        float l0 = dot4(cf4, __ldg(&mv[sub]))      + dot4(pf4, __ldg(&mv[16 + sub]));
        float l1 = dot4(cf4, __ldg(&mv[32 + sub])) + dot4(pf4, __ldg(&mv[48 + sub]));
        #pragma unroll
        for (int off = 1; off <= 8; off <<= 1) {
            l0 += __shfl_xor_sync(0xffffffffu, l0, off);
            l1 += __shfl_xor_sync(0xffffffffu, l1, off);
        }
        if (sub == 0) {
            float inv0 = __ldg(&mom_gamma[0]) / sqrtf(__ldg(&mom_var[0]) + BN_EPS);
            float inv1 = __ldg(&mom_gamma[1]) / sqrtf(__ldg(&mom_var[1]) + BN_EPS);
            float m0 = (l0 - __ldg(&mom_mean[0])) * inv0 + __ldg(&mom_beta[0]);
            float m1 = (l1 - __ldg(&mom_mean[1])) * inv1 + __ldg(&mom_beta[1]);
            float mx = fmaxf(m0, m1);
            float e0 = expf(m0 - mx), e1 = expf(m1 - mx);
            float s = e0 + e1;
            g_S[b * 1024 + n]       = e0 / s;
            g_S[b * 1024 + 512 + n] = e1 / s;
        }
    }
}

// ---------------- reorder: g_curves[step][w][ch] -> out[b][ch][n][step] ----------------
__global__ __launch_bounds__(256)
void reorder_kernel(float* __restrict__ out) {
    __shared__ float tile[16][8 * C + 1];
    int b = blockIdx.x >> 5;
    int n0 = (blockIdx.x & 31) * 16;
    int t = threadIdx.x;

    #pragma unroll
    for (int step = 0; step < STEPS; step++) {
        #pragma unroll
        for (int i4 = 0; i4 < 4; i4++) {
            int i = i4 * 4 + (t >> 6);
            int ch = t & 63;
            int w = b * CN + n0 + i;
            tile[i][step * 64 + ch] =
                g_curves[((size_t)step * NW + w) * C + ch];
        }
    }
    __syncthreads();

    int i = t & 15, ch0 = t >> 4;
    #pragma unroll
    for (int cc = 0; cc < 4; cc++) {
        int ch = ch0 + cc * 16;
        float v[8];
        #pragma unroll
        for (int s = 0; s < STEPS; s++) v[s] = tile[i][s * 64 + ch];
        float4* dst = (float4*)(out +
            ((((size_t)b * C + ch) * CN) + n0 + i) * STEPS);
        dst[0] = make_float4(v[0], v[1], v[2], v[3]);
        dst[1] = make_float4(v[4], v[5], v[6], v[7]);
    }
}

extern "C" void kernel_launch(void* const* d_in, const int* in_sizes, int n_in,
                              void* d_out, int out_size) {
    const float* x          = (const float*)d_in[1];
    const int*   adj        = (const int*)  d_in[2];
    const int*   cur        = (const int*)  d_in[3];
    const float* agent_w    = (const float*)d_in[4];
    const float* agent_gamma= (const float*)d_in[5];
    const float* agent_beta = (const float*)d_in[6];
    const float* agent_mean = (const float*)d_in[7];
    const float* agent_var  = (const float*)d_in[8];
    const float* mom_w      = (const float*)d_in[9];
    const float* mom_gamma  = (const float*)d_in[10];
    const float* mom_beta   = (const float*)d_in[11];
    const float* mom_mean   = (const float*)d_in[12];
    const float* mom_var    = (const float*)d_in[13];
    float* out = (float*)d_out;

    dim3 pg(TOT / 32, BN);
    prep_kernel<<<pg, 256>>>(x, agent_w);

    int blocks = NW / 8;   // 1024 blocks of 128 threads (16 lanes/walker)
    walk_step_kernel<true><<<blocks, 128>>>(adj, cur, agent_w, agent_gamma,
        agent_beta, agent_mean, agent_var, mom_w, mom_gamma, mom_beta,
        mom_mean, mom_var, 0);
    for (int s = 1; s < STEPS; s++) {
        walk_step_kernel<false><<<blocks, 128>>>(adj, cur, agent_w, agent_gamma,
            agent_beta, agent_mean, agent_var, mom_w, mom_gamma, mom_beta,
            mom_mean, mom_var, s);
    }
    reorder_kernel<<<BN * (CN / 16), 256>>>(out);
}

// round 17
// speedup vs baseline: 1.1990x; 1.0242x over previous
#include <cuda_runtime.h>
#include <cfloat>

#define TOT 8192
#define BN 16
#define C 64
#define K 20
#define CN 512
#define NW (BN*CN)
#define STEPS 8
#define BN_EPS 1e-5f
#define WSTR 400   // smem floats per walker: 22 cols x stride 17 = 374, pad->400

// ---- device scratch (static; no allocations) ----
__device__ float  g_xT[(size_t)BN*TOT*C];        // x transposed (b,node,ch) 32MB
__device__ float2 g_ssq[(size_t)BN*TOT];         // per-node (dot(x,w_lo), |x|^2)
__device__ float  g_curves[(size_t)STEPS*NW*C];  // [step][w][ch] 16MB
__device__ float  g_curf[(size_t)NW*C];
__device__ float  g_pref[(size_t)NW*C];
__device__ int    g_adjc[(size_t)NW*K];          // prefetched adj row of next node
__device__ float2 g_ssqc[(size_t)NW*K];          // prefetched ssq of those neighbors
__device__ float  g_S[BN*2*CN];                  // softmax exchange

__device__ __forceinline__ float dot4(const float4& a, const float4& b) {
    return a.x*b.x + a.y*b.y + a.z*b.z + a.w*b.w;
}

// ---------------- fused prep: transpose + per-node (s, |x|^2) (validated) ----
__global__ __launch_bounds__(256)
void prep_kernel(const float* __restrict__ x, const float* __restrict__ agent_w) {
    cudaTriggerProgrammaticLaunchCompletion();   // let step0 pre-launch
    __shared__ float tile[64][33];
    int b = blockIdx.y;
    int node0 = blockIdx.x * 32;
    int t = threadIdx.x;
    int ty = t >> 3;
    int tx = t & 7;

    const float* xb = x + (size_t)b * C * TOT;
    float4 v0 = __ldg((const float4*)(xb + (size_t)ty * TOT + node0) + tx);
    float4 v1 = __ldg((const float4*)(xb + (size_t)(ty + 32) * TOT + node0) + tx);
    tile[ty][tx*4+0] = v0.x; tile[ty][tx*4+1] = v0.y;
    tile[ty][tx*4+2] = v0.z; tile[ty][tx*4+3] = v0.w;
    tile[ty+32][tx*4+0] = v1.x; tile[ty+32][tx*4+1] = v1.y;
    tile[ty+32][tx*4+2] = v1.z; tile[ty+32][tx*4+3] = v1.w;
    __syncthreads();

    int node = t >> 3;
    int j = t & 7;
    float4 a = make_float4(tile[4*j+0][node], tile[4*j+1][node],
                           tile[4*j+2][node], tile[4*j+3][node]);
    float4 c = make_float4(tile[32+4*j+0][node], tile[32+4*j+1][node],
                           tile[32+4*j+2][node], tile[32+4*j+3][node]);
    float4* dst = (float4*)(g_xT + ((size_t)b * TOT + node0 + node) * C);
    dst[j] = a; dst[8 + j] = c;

    const float4* wv = (const float4*)agent_w;
    float4 wA = __ldg(&wv[j]), wB = __ldg(&wv[8 + j]);
    float s = dot4(a, wA) + dot4(c, wB);
    float q = dot4(a, a) + dot4(c, c);
    #pragma unroll
    for (int off = 1; off <= 4; off <<= 1) {
        s += __shfl_xor_sync(0xffffffffu, s, off);
        q += __shfl_xor_sync(0xffffffffu, q, off);
    }
    if (j == 0) g_ssq[(size_t)b * TOT + node0 + node] = make_float2(s, q);
}

// ---------------- one walk step; 16 lanes/walker, 8 walkers/block (R16 body) ----
// PDL: trigger early; gridDependencySynchronize before any dependent-data read.
template<bool FIRST>
__global__ __launch_bounds__(128)
void walk_step_kernel(
    const int* __restrict__ adj, const int* __restrict__ cur0,
    const float* __restrict__ agent_w,
    const float* __restrict__ agent_gamma, const float* __restrict__ agent_beta,
    const float* __restrict__ agent_mean,  const float* __restrict__ agent_var,
    const float* __restrict__ mom_w,
    const float* __restrict__ mom_gamma, const float* __restrict__ mom_beta,
    const float* __restrict__ mom_mean,  const float* __restrict__ mom_var,
    int step)
{
    cudaTriggerProgrammaticLaunchCompletion();   // let next step pre-launch

    __shared__ float sm[8 * WSTR];
    int sub = threadIdx.x & 15;
    int wi  = threadIdx.x >> 4;
    int w = blockIdx.x * 8 + wi;
    int b = w >> 9;
    int n = w & 511;
    int smb = wi * WSTR;

    // ---- independent preamble (overlaps predecessor's tail) ----
    const float4* wv = (const float4*)agent_w;
    float4 wh = __ldg(&wv[16 + sub]);              // agent_w[64:128]
    float inv_a  = __ldg(agent_gamma) / sqrtf(__ldg(agent_var) + BN_EPS);
    float mean_a = __ldg(agent_mean);
    float beta_a = __ldg(agent_beta);

    // ---- wait for predecessor's writes (g_xT/g_ssq/g_curf/g_pref/g_S/g_adjc) ----
    cudaGridDependencySynchronize();

    const float* xTb = g_xT + (size_t)b * TOT * C;
    const float2* ssqb = g_ssq + (size_t)b * TOT;

    float4 cf4, pf4, cv4;
    float tpp, n1 = 0.f;

    const int* adjc;
    float2 q0, q1;

    if (FIRST) {
        int cidx = __ldg(&cur0[w]);
        pf4 = __ldg(&((const float4*)(xTb + (size_t)cidx * C))[sub]);
        tpp = dot4(pf4, wh);
        #pragma unroll
        for (int off = 1; off <= 8; off <<= 1)
            tpp += __shfl_xor_sync(0xffffffffu, tpp, off);
        cf4 = make_float4(0.f,0.f,0.f,0.f); cv4 = cf4;
        adjc = adj + ((size_t)b * TOT + cidx) * K;
        int oa0 = __ldg(&adjc[sub]);
        int oa1 = (sub < 4) ? __ldg(&adjc[16 + sub]) : oa0;
        q0 = __ldg(&ssqb[oa0]);
        q1 = __ldg(&ssqb[oa1]);
    } else {
        adjc = g_adjc + (size_t)w * K;
        q0 = g_ssqc[(size_t)w * K + sub];
        q1 = (sub < 4) ? g_ssqc[(size_t)w * K + 16 + sub] : q0;

        cf4 = ((const float4*)(g_curf + (size_t)w * C))[sub];
        pf4 = ((const float4*)(g_pref + (size_t)w * C))[sub];
        float2 aa = ((const float2*)g_S)[b * 512 + n];   // entries 2n, 2n+1
        float a0 = aa.x, a1 = aa.y;
        pf4.x = cf4.x*a0 + pf4.x*a1;  pf4.y = cf4.y*a0 + pf4.y*a1;
        pf4.z = cf4.z*a0 + pf4.z*a1;  pf4.w = cf4.w*a0 + pf4.w*a1;
        cv4.x = cf4.x - pf4.x; cv4.y = cf4.y - pf4.y;
        cv4.z = cf4.z - pf4.z; cv4.w = cf4.w - pf4.w;

        float tppp = dot4(pf4, wh);
        float n1pp = dot4(cv4, cv4);
        #pragma unroll
        for (int off = 1; off <= 8; off <<= 1) {
            tppp += __shfl_xor_sync(0xffffffffu, tppp, off);
            n1pp += __shfl_xor_sync(0xffffffffu, n1pp, off);
        }
        tpp = tppp; n1 = sqrtf(n1pp);
    }

    float best; int ksel;

    if (FIRST) {
        best = (q0.x + tpp - mean_a) * inv_a + beta_a;  ksel = sub;
        if (sub < 4) {
            float l1 = (q1.x + tpp - mean_a) * inv_a + beta_a;
            if (l1 > best) { best = l1; ksel = 16 + sub; }
        }
    } else {
        // ---- gather 20 rows (256B coalesced each, full MLP) ----
        const int4* adj4 = (const int4*)adjc;
        float cfp[K];
        #pragma unroll
        for (int q = 0; q < 5; q++) {
            int4 t4 = adj4[q];
            float4 p0 = __ldg(&((const float4*)(xTb + (size_t)t4.x * C))[sub]);
            float4 p1 = __ldg(&((const float4*)(xTb + (size_t)t4.y * C))[sub]);
            float4 p2 = __ldg(&((const float4*)(xTb + (size_t)t4.z * C))[sub]);
            float4 p3 = __ldg(&((const float4*)(xTb + (size_t)t4.w * C))[sub]);
            sm[smb + 17*(4*q+0) + sub] = dot4(cv4, p0);
            sm[smb + 17*(4*q+1) + sub] = dot4(cv4, p1);
            sm[smb + 17*(4*q+2) + sub] = dot4(cv4, p2);
            sm[smb + 17*(4*q+3) + sub] = dot4(cv4, p3);
            cfp[4*q+0] = dot4(cf4, p0);
            cfp[4*q+1] = dot4(cf4, p1);
            cfp[4*q+2] = dot4(cf4, p2);
            cfp[4*q+3] = dot4(cf4, p3);
        }
        // cvcf / cf2 through SAME tree (=> cc exactly 0 on self-neighbors)
        sm[smb + 17*20 + sub] = dot4(cv4, cf4);
        sm[smb + 17*21 + sub] = dot4(cf4, cf4);
        __syncwarp();

        // ---- phase A: 16-way serial column sums (fixed order) for cv side ----
        int cS1 = (sub < 6) ? (16 + sub) : sub;
        float S0 = 0.f, S1 = 0.f;
        #pragma unroll
        for (int i = 0; i < 16; i++) {
            S0 += sm[smb + 17*sub + i];
            S1 += sm[smb + 17*cS1 + i];
        }
        float cvcf = __shfl_sync(0xffffffffu, S1, 4, 16);  // lane 4 owns col 20
        float cf2  = __shfl_sync(0xffffffffu, S1, 5, 16);  // lane 5 owns col 21
        __syncwarp();   // phase A reads complete before overwrite

        // ---- phase B: store cfp partials (constant cols), reduce ----
        #pragma unroll
        for (int k = 0; k < K; k++) sm[smb + 17*k + sub] = cfp[k];
        __syncwarp();
        int cT1 = (sub < 4) ? (16 + sub) : sub;
        float T0 = 0.f, T1 = 0.f;
        #pragma unroll
        for (int i = 0; i < 16; i++) {
            T0 += sm[smb + 17*sub + i];
            T1 += sm[smb + 17*cT1 + i];
        }

        // ---- lane-distributed epilogue (1-2 candidates per lane) ----
        {
            float lg = (q0.x + tpp - mean_a) * inv_a + beta_a;
            float cc = S0 - cvcf;
            float nn = q0.y - 2.f * T0 + cf2;
            float cosv = cc / fmaxf(n1 * sqrtf(nn), 1e-8f);
            lg *= fminf(fmaxf(1.f + cosv, 0.f), 1.f);
            best = lg; ksel = sub;
        }
        if (sub < 4) {
            float lg = (q1.x + tpp - mean_a) * inv_a + beta_a;
            float cc = S1 - cvcf;
            float nn = q1.y - 2.f * T1 + cf2;
            float cosv = cc / fmaxf(n1 * sqrtf(nn), 1e-8f);
            lg *= fminf(fmaxf(1.f + cosv, 0.f), 1.f);
            if (lg > best) { best = lg; ksel = 16 + sub; }
        }
    }

    // ---- argmax combine over 16 lanes (ties -> smallest k = first max) ----
    #pragma unroll
    for (int off = 1; off <= 8; off <<= 1) {
        float ob = __shfl_xor_sync(0xffffffffu, best, off);
        int   ok = __shfl_xor_sync(0xffffffffu, ksel, off);
        if (ob > best || (ob == best && ok < ksel)) { best = ob; ksel = ok; }
    }

    int nidx = FIRST ? __ldg(&adjc[ksel]) : adjc[ksel];
    cf4 = __ldg(&((const float4*)(xTb + (size_t)nidx * C))[sub]);

    // ---- coalesced curve store + persist state (256B rows) ----
    ((float4*)(g_curves + ((size_t)step * NW + w) * C))[sub] = cf4;
    ((float4*)(g_curf + (size_t)w * C))[sub] = cf4;
    ((float4*)(g_pref + (size_t)w * C))[sub] = pf4;

    if (step < STEPS - 1) {
        // ---- prefetch next step's adjacency + ssq (off the next critical path) ----
        {
            const int* adjn = adj + ((size_t)b * TOT + nidx) * K;
            int pa0 = __ldg(&adjn[sub]);
            g_adjc[(size_t)w * K + sub] = pa0;
            g_ssqc[(size_t)w * K + sub] = __ldg(&ssqb[pa0]);
            if (sub < 4) {
                int pa1 = __ldg(&adjn[16 + sub]);
                g_adjc[(size_t)w * K + 16 + sub] = pa1;
                g_ssqc[(size_t)w * K + 16 + sub] = __ldg(&ssqb[pa1]);
            }
        }

        const float4* mv = (const float4*)mom_w;   // 2 rows x 32 float4
        float l0 = dot4(cf4, __ldg(&mv[sub]))      + dot4(pf4, __ldg(&mv[16 + sub]));
        float l1 = dot4(cf4, __ldg(&mv[32 + sub])) + dot4(pf4, __ldg(&mv[48 + sub]));
        #pragma unroll
        for (int off = 1; off <= 8; off <<= 1) {
            l0 += __shfl_xor_sync(0xffffffffu, l0, off);
            l1 += __shfl_xor_sync(0xffffffffu, l1, off);
        }
        if (sub == 0) {
            float inv0 = __ldg(&mom_gamma[0]) / sqrtf(__ldg(&mom_var[0]) + BN_EPS);
            float inv1 = __ldg(&mom_gamma[1]) / sqrtf(__ldg(&mom_var[1]) + BN_EPS);
            float m0 = (l0 - __ldg(&mom_mean[0])) * inv0 + __ldg(&mom_beta[0]);
            float m1 = (l1 - __ldg(&mom_mean[1])) * inv1 + __ldg(&mom_beta[1]);
            float mx = fmaxf(m0, m1);
            float e0 = expf(m0 - mx), e1 = expf(m1 - mx);
            float s = e0 + e1;
            g_S[b * 1024 + n]       = e0 / s;
            g_S[b * 1024 + 512 + n] = e1 / s;
        }
    }
}

// ---------------- reorder: g_curves[step][w][ch] -> out[b][ch][n][step] ----------------
__global__ __launch_bounds__(256)
void reorder_kernel(float* __restrict__ out) {
    __shared__ float tile[16][8 * C + 1];
    int b = blockIdx.x >> 5;
    int n0 = (blockIdx.x & 31) * 16;
    int t = threadIdx.x;

    cudaGridDependencySynchronize();   // wait for final walk step's g_curves

    #pragma unroll
    for (int step = 0; step < STEPS; step++) {
        #pragma unroll
        for (int i4 = 0; i4 < 4; i4++) {
            int i = i4 * 4 + (t >> 6);
            int ch = t & 63;
            int w = b * CN + n0 + i;
            tile[i][step * 64 + ch] =
                g_curves[((size_t)step * NW + w) * C + ch];
        }
    }
    __syncthreads();

    int i = t & 15, ch0 = t >> 4;
    #pragma unroll
    for (int cc = 0; cc < 4; cc++) {
        int ch = ch0 + cc * 16;
        float v[8];
        #pragma unroll
        for (int s = 0; s < STEPS; s++) v[s] = tile[i][s * 64 + ch];
        float4* dst = (float4*)(out +
            ((((size_t)b * C + ch) * CN) + n0 + i) * STEPS);
        dst[0] = make_float4(v[0], v[1], v[2], v[3]);
        dst[1] = make_float4(v[4], v[5], v[6], v[7]);
    }
}

// host-side PDL launch helper
template <typename F, typename... Args>
static void launch_pdl(F f, dim3 grid, dim3 block, Args... args) {
    cudaLaunchConfig_t cfg = {};
    cfg.gridDim = grid;
    cfg.blockDim = block;
    cudaLaunchAttribute attr[1];
    attr[0].id = cudaLaunchAttributeProgrammaticStreamSerialization;
    attr[0].val.programmaticStreamSerializationAllowed = 1;
    cfg.attrs = attr;
    cfg.numAttrs = 1;
    cudaLaunchKernelEx(&cfg, f, args...);
}

extern "C" void kernel_launch(void* const* d_in, const int* in_sizes, int n_in,
                              void* d_out, int out_size) {
    const float* x          = (const float*)d_in[1];
    const int*   adj        = (const int*)  d_in[2];
    const int*   cur        = (const int*)  d_in[3];
    const float* agent_w    = (const float*)d_in[4];
    const float* agent_gamma= (const float*)d_in[5];
    const float* agent_beta = (const float*)d_in[6];
    const float* agent_mean = (const float*)d_in[7];
    const float* agent_var  = (const float*)d_in[8];
    const float* mom_w      = (const float*)d_in[9];
    const float* mom_gamma  = (const float*)d_in[10];
    const float* mom_beta   = (const float*)d_in[11];
    const float* mom_mean   = (const float*)d_in[12];
    const float* mom_var    = (const float*)d_in[13];
    float* out = (float*)d_out;

    dim3 pg(TOT / 32, BN);
    prep_kernel<<<pg, 256>>>(x, agent_w);

    int blocks = NW / 8;   // 1024 blocks of 128 threads (16 lanes/walker)
    launch_pdl(walk_step_kernel<true>, dim3(blocks), dim3(128),
        adj, cur, agent_w, agent_gamma, agent_beta, agent_mean, agent_var,
        mom_w, mom_gamma, mom_beta, mom_mean, mom_var, 0);
    for (int s = 1; s < STEPS; s++) {
        launch_pdl(walk_step_kernel<false>, dim3(blocks), dim3(128),
            adj, cur, agent_w, agent_gamma, agent_beta, agent_mean, agent_var,
            mom_w, mom_gamma, mom_beta, mom_mean, mom_var, s);
    }
    launch_pdl(reorder_kernel, dim3(BN * (CN / 16)), dim3(256), out);
}